// round 11
// baseline (speedup 1.0000x reference)
#include <cuda_runtime.h>
#include <math.h>
#include <stdint.h>

#define NN   300000
#define NE   299999
#define NA   150000
#define DD   64
#define HH   128

// ---------------- scratch ----------------
__device__ float g_h   [(size_t)NN * HH];
__device__ float g_xl  [(size_t)NN * HH];
__device__ float g_xr  [(size_t)NN * HH];
__device__ float g_acc [(size_t)NN * HH];
__device__ float g_den [NN];
__device__ float g_cadd[HH];

// ---------------- tf32 helpers ----------------
__device__ __forceinline__ uint32_t f2tf32(float f)
{
    uint32_t u;
    asm("cvt.rna.tf32.f32 %0, %1;" : "=r"(u) : "f"(f));
    return u;
}
__device__ __forceinline__ float tf32f(float f) { return __uint_as_float(f2tf32(f)); }

__device__ __forceinline__ void mma_tf32(float* d, const uint32_t* a, const uint32_t* b)
{
    asm volatile(
        "mma.sync.aligned.m16n8k8.row.col.f32.tf32.tf32.f32 "
        "{%0,%1,%2,%3},{%4,%5,%6,%7},{%8,%9},{%0,%1,%2,%3};"
        : "+f"(d[0]), "+f"(d[1]), "+f"(d[2]), "+f"(d[3])
        : "r"(a[0]), "r"(a[1]), "r"(a[2]), "r"(a[3]), "r"(b[0]), "r"(b[1]));
}

#define WNP 136     // W smem pitch (64-row chunk)
#define AP  132     // A pitch (K=128)
#define APH 260     // A pitch (K=256, head)

// single-W mainloop over one 64-k chunk. Warp tile (MF*16) x (NF*8).
template <int MF, int NF>
__device__ __forceinline__ void mma_chunk64(
    const float* As, int KP, int a_off, const float* Ws,
    int wrow, int wcol, int gid, int tig, float acc[MF][NF][4])
{
#pragma unroll
    for (int ks = 0; ks < 8; ++ks) {
        const int k0 = ks * 8;
        uint32_t a[MF][4], b[NF][2];
#pragma unroll
        for (int mf = 0; mf < MF; ++mf) {
            const float* ap = As + (wrow + mf * 16 + gid) * KP + a_off + k0;
            a[mf][0] = __float_as_uint(ap[tig]);
            a[mf][1] = __float_as_uint(ap[8 * KP + tig]);
            a[mf][2] = __float_as_uint(ap[tig + 4]);
            a[mf][3] = __float_as_uint(ap[8 * KP + tig + 4]);
        }
#pragma unroll
        for (int nf = 0; nf < NF; ++nf) {
            const int c = wcol + nf * 8 + gid;
            b[nf][0] = __float_as_uint(Ws[(k0 + tig) * WNP + c]);
            b[nf][1] = __float_as_uint(Ws[(k0 + tig + 4) * WNP + c]);
        }
#pragma unroll
        for (int mf = 0; mf < MF; ++mf)
#pragma unroll
            for (int nf = 0; nf < NF; ++nf)
                mma_tf32(acc[mf][nf], a[mf], b[nf]);
    }
}

// dual-W mainloop: A-fragments shared across BOTH W matrices (2 LDS/mma)
__device__ __forceinline__ void mma_chunk64_dual(
    const float* As, int a_off,
    const float* Ws0, const float* Ws1,
    int wrow, int wcol, int gid, int tig,
    float acc0[2][4][4], float acc1[2][4][4])
{
#pragma unroll
    for (int ks = 0; ks < 8; ++ks) {
        const int k0 = ks * 8;
        uint32_t a[2][4], b0[4][2], b1[4][2];
#pragma unroll
        for (int mf = 0; mf < 2; ++mf) {
            const float* ap = As + (wrow + mf * 16 + gid) * AP + a_off + k0;
            a[mf][0] = __float_as_uint(ap[tig]);
            a[mf][1] = __float_as_uint(ap[8 * AP + tig]);
            a[mf][2] = __float_as_uint(ap[tig + 4]);
            a[mf][3] = __float_as_uint(ap[8 * AP + tig + 4]);
        }
#pragma unroll
        for (int nf = 0; nf < 4; ++nf) {
            const int c = wcol + nf * 8 + gid;
            b0[nf][0] = __float_as_uint(Ws0[(k0 + tig) * WNP + c]);
            b0[nf][1] = __float_as_uint(Ws0[(k0 + tig + 4) * WNP + c]);
            b1[nf][0] = __float_as_uint(Ws1[(k0 + tig) * WNP + c]);
            b1[nf][1] = __float_as_uint(Ws1[(k0 + tig + 4) * WNP + c]);
        }
#pragma unroll
        for (int mf = 0; mf < 2; ++mf)
#pragma unroll
            for (int nf = 0; nf < 4; ++nf) {
                mma_tf32(acc0[mf][nf], a[mf], b0[nf]);
                mma_tf32(acc1[mf][nf], a[mf], b1[nf]);
            }
    }
}

// stage one 64-row W chunk [64 x 128] -> Ws (tf32), 256-thread block
__device__ __forceinline__ void stage_w64(const float* __restrict__ W, float* Ws, int tid)
{
    for (int i = tid; i < 64 * 32; i += 256) {
        int k = i >> 5, c4 = i & 31;
        float4 v = ((const float4*)W)[i];
        float* wp = Ws + k * WNP + c4 * 4;
        wp[0] = tf32f(v.x); wp[1] = tf32f(v.y); wp[2] = tf32f(v.z); wp[3] = tf32f(v.w);
    }
}

#define ZACC(acc, MF, NF)                             \
    _Pragma("unroll") for (int mf = 0; mf < MF; ++mf) \
    _Pragma("unroll") for (int nf = 0; nf < NF; ++nf) \
    _Pragma("unroll") for (int j = 0; j < 4; ++j) acc[mf][nf][j] = 0.f;

// epilogue for dual kernels: write one phase's acc (+bias) to C
__device__ __forceinline__ void write_c(
    float* __restrict__ C, const float* __restrict__ bias,
    int row0, int wrow, int wcol, int gid, int tig,
    float acc[2][4][4], int M)
{
#pragma unroll
    for (int nf = 0; nf < 4; ++nf) {
        const int c = wcol + nf * 8 + tig * 2;
        const float b0 = bias[c], b1 = bias[c + 1];
#pragma unroll
        for (int mf = 0; mf < 2; ++mf)
#pragma unroll
            for (int h = 0; h < 2; ++h) {
                const int r = row0 + wrow + mf * 16 + h * 8 + gid;
                if (r < M)
                    *(float2*)(C + (size_t)r * 128 + c) =
                        make_float2(acc[mf][nf][2 * h] + b0, acc[mf][nf][2 * h + 1] + b1);
            }
    }
}

// ---------- fused embed + dual transform (BM=64, dual-W phase, 2 CTAs/SM) ----------
__global__ __launch_bounds__(256, 2) void embed_dual(
    const float* __restrict__ x,
    const float* __restrict__ We, const float* __restrict__ be,
    const float* __restrict__ Wl, const float* __restrict__ bl,
    const float* __restrict__ Wr, const float* __restrict__ br,
    float* __restrict__ Hout, float* __restrict__ Cl, float* __restrict__ Cr,
    float* __restrict__ Accz, float* __restrict__ Denz, int M)
{
    extern __shared__ float sh[];
    float* As  = sh;                   // 64 x AP (phase A uses pitch 68)
    float* Ws0 = sh + 64 * AP;         // 64 x WNP
    float* Ws1 = Ws0 + 64 * WNP;       // 64 x WNP
    const int tid = threadIdx.x;
    const int row0 = blockIdx.x * 64;

    // zero this block's slice of acc and den (for the following edge pass)
    {
        const float4 z4 = make_float4(0.f, 0.f, 0.f, 0.f);
        int nrow = min(64, M - row0);
        for (int i = tid; i < nrow * 32; i += 256)
            ((float4*)Accz)[(size_t)row0 * 32 + i] = z4;
        if (tid < nrow) Denz[row0 + tid] = 0.f;
    }

    // phase A: stage W_embed (64 rows) + x (pitch 68)
    stage_w64(We, Ws0, tid);
    for (int i = tid; i < 64 * 16; i += 256) {
        int r = i >> 4, c4 = i & 15;
        int gr = row0 + r;
        float4 v = make_float4(0.f, 0.f, 0.f, 0.f);
        if (gr < M) v = ((const float4*)(x + (size_t)gr * 64))[c4];
        float* ap = As + r * 68 + c4 * 4;
        ap[0] = tf32f(v.x); ap[1] = tf32f(v.y); ap[2] = tf32f(v.z); ap[3] = tf32f(v.w);
    }
    __syncthreads();

    const int wid = tid >> 5, lane = tid & 31;
    const int wm = wid & 1, wn = wid >> 1;          // 2x4 warp grid, tile 32x32
    const int wrow = wm * 32, wcol = wn * 32;
    const int gid = lane >> 2, tig = lane & 3;

    float acc0[2][4][4], acc1[2][4][4];
    ZACC(acc0, 2, 4)
    mma_chunk64<2, 4>(As, 68, 0, Ws0, wrow, wcol, gid, tig, acc0);
    __syncthreads();   // phase-A reads complete before As/Ws0 overwrite

    // epilogue h: write gmem + restage tf32 into As (pitch AP)
#pragma unroll
    for (int nf = 0; nf < 4; ++nf) {
        const int c = wcol + nf * 8 + tig * 2;
        const float b0 = be[c], b1 = be[c + 1];
#pragma unroll
        for (int mf = 0; mf < 2; ++mf)
#pragma unroll
            for (int h = 0; h < 2; ++h) {
                const int rl = wrow + mf * 16 + h * 8 + gid;
                const float v0 = acc0[mf][nf][2 * h] + b0;
                const float v1 = acc0[mf][nf][2 * h + 1] + b1;
                const int gr = row0 + rl;
                if (gr < M)
                    *(float2*)(Hout + (size_t)gr * 128 + c) = make_float2(v0, v1);
                As[rl * AP + c]     = tf32f(v0);
                As[rl * AP + c + 1] = tf32f(v1);
            }
    }

    // phase B: dual GEMM (Wl, Wr) sharing A fragments
    ZACC(acc0, 2, 4)
    ZACC(acc1, 2, 4)
#pragma unroll
    for (int kc = 0; kc < 2; ++kc) {
        __syncthreads();                 // guard epilogue As writes / prior Ws reads
        stage_w64(Wl + kc * 64 * 128, Ws0, tid);
        stage_w64(Wr + kc * 64 * 128, Ws1, tid);
        __syncthreads();
        mma_chunk64_dual(As, kc * 64, Ws0, Ws1, wrow, wcol, gid, tig, acc0, acc1);
    }
    write_c(Cl, bl, row0, wrow, wcol, gid, tig, acc0, M);
    write_c(Cr, br, row0, wrow, wcol, gid, tig, acc1, M);
}

// ---------- dual transform with fused update + zero-after-read (dual-W, 2 CTAs/SM) ----------
__global__ __launch_bounds__(256, 2) void dual_upd(
    float* __restrict__ H, float* __restrict__ Acc, float* __restrict__ Den,
    const float* __restrict__ ubias,
    const float* __restrict__ Wl, const float* __restrict__ bl,
    const float* __restrict__ Wr, const float* __restrict__ br,
    float* __restrict__ Cl, float* __restrict__ Cr, int M)
{
    extern __shared__ float sh[];
    float* As  = sh;                   // 64 x AP
    float* Ws0 = sh + 64 * AP;         // 64 x WNP
    float* Ws1 = Ws0 + 64 * WNP;       // 64 x WNP
    const int tid = threadIdx.x;
    const int row0 = blockIdx.x * 64;

    // stage A with fused update: h1 = h + relu(acc/den + ubias)
    for (int i = tid; i < 64 * 32; i += 256) {
        int r = i >> 5, c4 = i & 31;
        int gr = row0 + r;
        float4 hv = make_float4(0.f, 0.f, 0.f, 0.f);
        if (gr < M) {
            float inv = 1.f / (Den[gr] + 1e-16f);
            float4 a = ((const float4*)Acc)[(size_t)gr * 32 + c4];
            hv = ((const float4*)H)[(size_t)gr * 32 + c4];
            const float4 bb = ((const float4*)ubias)[c4];
            hv.x += fmaxf(a.x * inv + bb.x, 0.f);
            hv.y += fmaxf(a.y * inv + bb.y, 0.f);
            hv.z += fmaxf(a.z * inv + bb.z, 0.f);
            hv.w += fmaxf(a.w * inv + bb.w, 0.f);
            ((float4*)H)[(size_t)gr * 32 + c4] = hv;
        }
        float* ap = As + r * AP + c4 * 4;
        ap[0] = tf32f(hv.x); ap[1] = tf32f(hv.y); ap[2] = tf32f(hv.z); ap[3] = tf32f(hv.w);
    }
    __syncthreads();   // ALL acc/den reads for this block's rows are complete

    // zero-after-read: re-zero acc/den for the next edge pass
    {
        const float4 z4 = make_float4(0.f, 0.f, 0.f, 0.f);
        int nrow = min(64, M - row0);
        for (int i = tid; i < nrow * 32; i += 256)
            ((float4*)Acc)[(size_t)row0 * 32 + i] = z4;
        if (tid < nrow) Den[row0 + tid] = 0.f;
    }

    const int wid = tid >> 5, lane = tid & 31;
    const int wm = wid & 1, wn = wid >> 1;
    const int wrow = wm * 32, wcol = wn * 32;
    const int gid = lane >> 2, tig = lane & 3;

    float acc0[2][4][4], acc1[2][4][4];
    ZACC(acc0, 2, 4)
    ZACC(acc1, 2, 4)
#pragma unroll
    for (int kc = 0; kc < 2; ++kc) {
        __syncthreads();
        stage_w64(Wl + kc * 64 * 128, Ws0, tid);
        stage_w64(Wr + kc * 64 * 128, Ws1, tid);
        __syncthreads();
        mma_chunk64_dual(As, kc * 64, Ws0, Ws1, wrow, wcol, gid, tig, acc0, acc1);
    }
    write_c(Cl, bl, row0, wrow, wcol, gid, tig, acc0, M);
    write_c(Cr, br, row0, wrow, wcol, gid, tig, acc1, M);
}

// ---------- fused edge pass: warp per edge ----------
__global__ void edge_kernel(const int* __restrict__ src, const int* __restrict__ dst,
                            const float* __restrict__ att)
{
    int e = (int)(((size_t)blockIdx.x * blockDim.x + threadIdx.x) >> 5);
    if (e >= NE) return;
    int ln = threadIdx.x & 31;
    int s = src[e], d = dst[e];
    float4 xa = ((const float4*)g_xl)[(size_t)s * 32 + ln];
    float4 xb = ((const float4*)g_xr)[(size_t)d * 32 + ln];
    float4 at = ((const float4*)att)[ln];
    float ex, ey, ez, ew;
    ex = xa.x + xb.x; ey = xa.y + xb.y; ez = xa.z + xb.z; ew = xa.w + xb.w;
    ex = ex > 0.f ? ex : 0.2f * ex;
    ey = ey > 0.f ? ey : 0.2f * ey;
    ez = ez > 0.f ? ez : 0.2f * ez;
    ew = ew > 0.f ? ew : 0.2f * ew;
    float p = ex * at.x + ey * at.y + ez * at.z + ew * at.w;
#pragma unroll
    for (int o = 16; o > 0; o >>= 1) p += __shfl_xor_sync(0xffffffffu, p, o);
    float e_ = __expf(p);
    if (ln == 0) atomicAdd(&g_den[d], e_);
    float* accd = g_acc + (size_t)d * 128 + ln * 4;
    atomicAdd(accd + 0, e_ * xa.x);
    atomicAdd(accd + 1, e_ * xa.y);
    atomicAdd(accd + 2, e_ * xa.z);
    atomicAdd(accd + 3, e_ * xa.w);
}

// ---------- mega head: BM=64, warp tile 32x32 grid 2x4, 2 CTAs/SM ----------
__global__ __launch_bounds__(256, 2) void head_kernel(
    const float* __restrict__ H, const float* __restrict__ Acc, const float* __restrict__ Den,
    const float* __restrict__ ubias,
    const int* __restrict__ child, const int* __restrict__ parent,
    const float* __restrict__ ttab, const int* __restrict__ timei,
    const float* __restrict__ W_comb, const float* __restrict__ b_comb,
    const float* __restrict__ W_a1, const float* __restrict__ cadd,
    const float* __restrict__ W_a2, const float* __restrict__ b_a2,
    float* __restrict__ out, int M)
{
    extern __shared__ float sh[];
    float* As  = sh;                  // 64 x APH
    float* Ws  = sh + 64 * APH;       // 64 x WNP
    float* red = Ws + 64 * WNP;       // 4 x 64
    const int tid = threadIdx.x;
    const int row0 = blockIdx.x * 64;

    // stage cat(h2[child], h2[parent]|0), h2 = h1 + relu(acc/den + ubias)
    for (int i = tid; i < 64 * 64; i += 256) {
        int r = i >> 6, c4 = i & 63;
        int gr = row0 + r;
        float4 v = make_float4(0.f, 0.f, 0.f, 0.f);
        if (gr < M) {
            int cc = c4 < 32 ? c4 : c4 - 32;
            int ri = c4 < 32 ? child[gr] : parent[gr];
            if (ri >= 0) {
                float inv = 1.f / (Den[ri] + 1e-16f);
                float4 a  = ((const float4*)Acc)[(size_t)ri * 32 + cc];
                v         = ((const float4*)H)[(size_t)ri * 32 + cc];
                float4 bb = ((const float4*)ubias)[cc];
                v.x += fmaxf(a.x * inv + bb.x, 0.f);
                v.y += fmaxf(a.y * inv + bb.y, 0.f);
                v.z += fmaxf(a.z * inv + bb.z, 0.f);
                v.w += fmaxf(a.w * inv + bb.w, 0.f);
            }
        }
        float* ap = As + r * APH + c4 * 4;
        ap[0] = tf32f(v.x); ap[1] = tf32f(v.y); ap[2] = tf32f(v.z); ap[3] = tf32f(v.w);
    }

    const int wid = tid >> 5, lane = tid & 31;
    const int wm = wid & 1, wn = wid >> 1;        // 2x4 warp grid, tile 32x32
    const int wrow = wm * 32, wcol = wn * 32;
    const int gid = lane >> 2, tig = lane & 3;

    float acc[2][4][4];
    ZACC(acc, 2, 4)

    // GEMM1: branch = cat @ W_comb  (K=256, 4 chunks)
#pragma unroll
    for (int kc = 0; kc < 4; ++kc) {
        __syncthreads();
        stage_w64(W_comb + kc * 64 * 128, Ws, tid);
        __syncthreads();
        mma_chunk64<2, 4>(As, APH, kc * 64, Ws, wrow, wcol, gid, tig, acc);
    }
    __syncthreads();   // GEMM1 As reads complete before overwrite

    // epilogue1: branch(+b_comb) -> As cols [0,128)
#pragma unroll
    for (int nf = 0; nf < 4; ++nf) {
        const int c = wcol + nf * 8 + tig * 2;
        const float b0 = b_comb[c], b1 = b_comb[c + 1];
#pragma unroll
        for (int mf = 0; mf < 2; ++mf)
#pragma unroll
            for (int h = 0; h < 2; ++h) {
                const int rl = wrow + mf * 16 + h * 8 + gid;
                As[rl * APH + c]     = tf32f(acc[mf][nf][2 * h]     + b0);
                As[rl * APH + c + 1] = tf32f(acc[mf][nf][2 * h + 1] + b1);
            }
    }
    // stage t_emb -> As cols [128,256)
    for (int i = tid; i < 64 * 32; i += 256) {
        int r = i >> 5, c4 = i & 31;
        int gr = row0 + r;
        float4 v = make_float4(0.f, 0.f, 0.f, 0.f);
        if (gr < M) {
            int t = timei[gr];
            v = ((const float4*)(ttab + (size_t)t * 128))[c4];
        }
        float* ap = As + r * APH + 128 + c4 * 4;
        ap[0] = tf32f(v.x); ap[1] = tf32f(v.y); ap[2] = tf32f(v.z); ap[3] = tf32f(v.w);
    }

    // GEMM2: hidden = relu(cat @ W_a1 + cadd)
    ZACC(acc, 2, 4)
#pragma unroll
    for (int kc = 0; kc < 4; ++kc) {
        __syncthreads();
        stage_w64(W_a1 + kc * 64 * 128, Ws, tid);
        __syncthreads();
        mma_chunk64<2, 4>(As, APH, kc * 64, Ws, wrow, wcol, gid, tig, acc);
    }

    // epilogue2: dot with W_a2
    float p[2][2] = {{0.f, 0.f}, {0.f, 0.f}};
#pragma unroll
    for (int nf = 0; nf < 4; ++nf) {
        const int c = wcol + nf * 8 + tig * 2;
        const float ca0 = cadd[c], ca1 = cadd[c + 1];
        const float w20 = W_a2[c], w21 = W_a2[c + 1];
#pragma unroll
        for (int mf = 0; mf < 2; ++mf)
#pragma unroll
            for (int h = 0; h < 2; ++h) {
                float v0 = fmaxf(acc[mf][nf][2 * h]     + ca0, 0.f);
                float v1 = fmaxf(acc[mf][nf][2 * h + 1] + ca1, 0.f);
                p[mf][h] += v0 * w20 + v1 * w21;
            }
    }
#pragma unroll
    for (int o = 1; o <= 2; o <<= 1)
#pragma unroll
        for (int mf = 0; mf < 2; ++mf)
#pragma unroll
            for (int h = 0; h < 2; ++h)
                p[mf][h] += __shfl_xor_sync(0xffffffffu, p[mf][h], o);

    __syncthreads();
    if (tig == 0) {
#pragma unroll
        for (int mf = 0; mf < 2; ++mf)
#pragma unroll
            for (int h = 0; h < 2; ++h)
                red[wn * 64 + wrow + mf * 16 + h * 8 + gid] = p[mf][h];
    }
    __syncthreads();
    if (tid < 64) {
        int gr = row0 + tid;
        if (gr < M)
            out[gr] = red[tid] + red[64 + tid] + red[128 + tid] + red[192 + tid] + b_a2[0];
    }
}

// ---------------- fused context precompute ----------------
__global__ void ctx_cadd_kernel(const float* __restrict__ focal, const float* __restrict__ W_seq,
                                const float* __restrict__ b_seq,
                                const float* __restrict__ W_a1, const float* __restrict__ b_a1)
{
    __shared__ float cs[128];
    int j = threadIdx.x;
    float s = b_seq[j];
    for (int d = 0; d < DD; ++d) s += focal[d] * W_seq[d * 128 + j];
    cs[j] = s;
    __syncthreads();
    float t = b_a1[j];
    for (int k = 0; k < 128; ++k) t += cs[k] * W_a1[(256 + k) * 128 + j];
    g_cadd[j] = t;
}

// ---------------- launch ----------------
extern "C" void kernel_launch(void* const* d_in, const int* in_sizes, int n_in,
                              void* d_out, int out_size)
{
    const float* x       = (const float*)d_in[0];
    const int*   ei      = (const int*)  d_in[1];
    const float* focal   = (const float*)d_in[2];
    const int*   child   = (const int*)  d_in[3];
    const int*   parent  = (const int*)  d_in[4];
    const int*   timei   = (const int*)  d_in[5];
    const float* W_embed = (const float*)d_in[6];
    const float* b_embed = (const float*)d_in[7];
    const float* bu_Wl   = (const float*)d_in[8];
    const float* bu_bl   = (const float*)d_in[9];
    const float* bu_Wr   = (const float*)d_in[10];
    const float* bu_br   = (const float*)d_in[11];
    const float* bu_att  = (const float*)d_in[12];
    const float* bu_bias = (const float*)d_in[13];
    const float* td_Wl   = (const float*)d_in[14];
    const float* td_bl   = (const float*)d_in[15];
    const float* td_Wr   = (const float*)d_in[16];
    const float* td_br   = (const float*)d_in[17];
    const float* td_att  = (const float*)d_in[18];
    const float* td_bias = (const float*)d_in[19];
    const float* ttab    = (const float*)d_in[20];
    const float* W_comb  = (const float*)d_in[21];
    const float* b_comb  = (const float*)d_in[22];
    const float* W_a1    = (const float*)d_in[23];
    const float* b_a1    = (const float*)d_in[24];
    const float* W_a2    = (const float*)d_in[25];
    const float* b_a2    = (const float*)d_in[26];
    const float* W_seq   = (const float*)d_in[27];
    const float* b_seq   = (const float*)d_in[28];
    float* out = (float*)d_out;

    const int SM_DUAL = (64 * AP + 2 * 64 * WNP) * 4;         // 103,424 B (2 CTAs/SM)
    const int SM_HEAD = (64 * APH + 64 * WNP + 256) * 4;      // 102,400 B (2 CTAs/SM)
    cudaFuncSetAttribute(embed_dual,  cudaFuncAttributeMaxDynamicSharedMemorySize, SM_DUAL);
    cudaFuncSetAttribute(dual_upd,    cudaFuncAttributeMaxDynamicSharedMemorySize, SM_DUAL);
    cudaFuncSetAttribute(head_kernel, cudaFuncAttributeMaxDynamicSharedMemorySize, SM_HEAD);

    float *hp, *xlp, *xrp, *accp, *denp, *caddp;
    cudaGetSymbolAddress((void**)&hp,    g_h);
    cudaGetSymbolAddress((void**)&xlp,   g_xl);
    cudaGetSymbolAddress((void**)&xrp,   g_xr);
    cudaGetSymbolAddress((void**)&accp,  g_acc);
    cudaGetSymbolAddress((void**)&denp,  g_den);
    cudaGetSymbolAddress((void**)&caddp, g_cadd);

    const int GEMM_BLKS_N = (NN + 63) / 64;
    const int HEAD_BLKS   = (NA + 63) / 64;
    const int EDGE_BLKS   = (NE + 7) / 8;

    // 0) context fold (tiny, no deps on pipeline)
    ctx_cadd_kernel<<<1, 128>>>(focal, W_seq, b_seq, W_a1, b_a1);

    // 1) embed + bottom-up transforms + acc/den zeroing (src = row1, dst = row0)
    embed_dual<<<GEMM_BLKS_N, 256, SM_DUAL>>>(x, W_embed, b_embed,
                                              bu_Wl, bu_bl, bu_Wr, bu_br,
                                              hp, xlp, xrp, accp, denp, NN);
    edge_kernel<<<EDGE_BLKS, 256>>>(ei + NE, ei, bu_att);

    // 2) update1 fused + top-down transforms + zero-after-read (src = row0, dst = row1)
    dual_upd<<<GEMM_BLKS_N, 256, SM_DUAL>>>(hp, accp, denp, bu_bias,
                                            td_Wl, td_bl, td_Wr, td_br,
                                            xlp, xrp, NN);
    edge_kernel<<<EDGE_BLKS, 256>>>(ei, ei + NE, td_att);

    // 3) head with on-the-fly update2
    head_kernel<<<HEAD_BLKS, 256, SM_HEAD>>>(hp, accp, denp, td_bias,
                                             child, parent, ttab, timei,
                                             W_comb, b_comb, W_a1, caddp,
                                             W_a2, b_a2, out, NA);
}

// round 12
// speedup vs baseline: 1.1781x; 1.1781x over previous
#include <cuda_runtime.h>
#include <cuda_fp16.h>
#include <math.h>
#include <stdint.h>

#define NN   300000
#define NE   299999
#define NA   150000
#define DD   64
#define HH   128

// ---------------- scratch ----------------
__device__ float  g_h   [(size_t)NN * HH];
__device__ __half g_xl  [(size_t)NN * HH];
__device__ __half g_xr  [(size_t)NN * HH];
__device__ __half g_acc [(size_t)NN * HH];
__device__ float  g_den [NN];
__device__ float  g_cadd[HH];

// ---------------- tf32 helpers ----------------
__device__ __forceinline__ uint32_t f2tf32(float f)
{
    uint32_t u;
    asm("cvt.rna.tf32.f32 %0, %1;" : "=r"(u) : "f"(f));
    return u;
}
__device__ __forceinline__ float tf32f(float f) { return __uint_as_float(f2tf32(f)); }

__device__ __forceinline__ void mma_tf32(float* d, const uint32_t* a, const uint32_t* b)
{
    asm volatile(
        "mma.sync.aligned.m16n8k8.row.col.f32.tf32.tf32.f32 "
        "{%0,%1,%2,%3},{%4,%5,%6,%7},{%8,%9},{%0,%1,%2,%3};"
        : "+f"(d[0]), "+f"(d[1]), "+f"(d[2]), "+f"(d[3])
        : "r"(a[0]), "r"(a[1]), "r"(a[2]), "r"(a[3]), "r"(b[0]), "r"(b[1]));
}

#define WNP 136     // W smem pitch (64-row chunk)
#define AP  132     // A pitch (K=128)
#define APH 260     // A pitch (K=256, head)

// mainloop over one 64-k chunk. Warp tile (MF*16) x (NF*8).
template <int MF, int NF>
__device__ __forceinline__ void mma_chunk64(
    const float* As, int KP, int a_off, const float* Ws,
    int wrow, int wcol, int gid, int tig, float acc[MF][NF][4])
{
#pragma unroll
    for (int ks = 0; ks < 8; ++ks) {
        const int k0 = ks * 8;
        uint32_t a[MF][4], b[NF][2];
#pragma unroll
        for (int mf = 0; mf < MF; ++mf) {
            const float* ap = As + (wrow + mf * 16 + gid) * KP + a_off + k0;
            a[mf][0] = __float_as_uint(ap[tig]);
            a[mf][1] = __float_as_uint(ap[8 * KP + tig]);
            a[mf][2] = __float_as_uint(ap[tig + 4]);
            a[mf][3] = __float_as_uint(ap[8 * KP + tig + 4]);
        }
#pragma unroll
        for (int nf = 0; nf < NF; ++nf) {
            const int c = wcol + nf * 8 + gid;
            b[nf][0] = __float_as_uint(Ws[(k0 + tig) * WNP + c]);
            b[nf][1] = __float_as_uint(Ws[(k0 + tig + 4) * WNP + c]);
        }
#pragma unroll
        for (int mf = 0; mf < MF; ++mf)
#pragma unroll
            for (int nf = 0; nf < NF; ++nf)
                mma_tf32(acc[mf][nf], a[mf], b[nf]);
    }
}

// stage one 64-row W chunk [64 x 128] -> Ws (tf32), 256-thread block
__device__ __forceinline__ void stage_w64(const float* __restrict__ W, float* Ws, int tid)
{
    for (int i = tid; i < 64 * 32; i += 256) {
        int k = i >> 5, c4 = i & 31;
        float4 v = ((const float4*)W)[i];
        float* wp = Ws + k * WNP + c4 * 4;
        wp[0] = tf32f(v.x); wp[1] = tf32f(v.y); wp[2] = tf32f(v.z); wp[3] = tf32f(v.w);
    }
}

#define ZACC(acc, MF, NF)                             \
    _Pragma("unroll") for (int mf = 0; mf < MF; ++mf) \
    _Pragma("unroll") for (int nf = 0; nf < NF; ++nf) \
    _Pragma("unroll") for (int j = 0; j < 4; ++j) acc[mf][nf][j] = 0.f;

// epilogue: write acc(+bias) to C as fp16 (one half2 per (c,c+1) pair)
__device__ __forceinline__ void write_c_h(
    __half* __restrict__ C, const float* __restrict__ bias,
    int row0, int wrow, int wcol, int gid, int tig,
    float acc[2][4][4], int M)
{
#pragma unroll
    for (int nf = 0; nf < 4; ++nf) {
        const int c = wcol + nf * 8 + tig * 2;
        const float b0 = bias[c], b1 = bias[c + 1];
#pragma unroll
        for (int mf = 0; mf < 2; ++mf)
#pragma unroll
            for (int h = 0; h < 2; ++h) {
                const int r = row0 + wrow + mf * 16 + h * 8 + gid;
                if (r < M)
                    *(__half2*)(C + (size_t)r * 128 + c) =
                        __floats2half2_rn(acc[mf][nf][2 * h] + b0, acc[mf][nf][2 * h + 1] + b1);
            }
    }
}

// ---------- fused embed + dual transform (BM=64, 3 CTAs/SM) + acc/den zeroing ----------
__global__ __launch_bounds__(256, 3) void embed_dual(
    const float* __restrict__ x,
    const float* __restrict__ We, const float* __restrict__ be,
    const float* __restrict__ Wl, const float* __restrict__ bl,
    const float* __restrict__ Wr, const float* __restrict__ br,
    float* __restrict__ Hout, __half* __restrict__ Cl, __half* __restrict__ Cr,
    __half* __restrict__ Accz, float* __restrict__ Denz, int M)
{
    extern __shared__ float sh[];
    float* As = sh;                  // 64 x AP (phase A uses pitch 68)
    float* Ws = sh + 64 * AP;        // 64 x WNP
    const int tid = threadIdx.x;
    const int row0 = blockIdx.x * 64;

    // zero this block's slice of acc (fp16) and den
    {
        const uint4 z = make_uint4(0u, 0u, 0u, 0u);
        int nrow = min(64, M - row0);
        for (int i = tid; i < nrow * 16; i += 256)          // 16 uint4 per 128-half row
            ((uint4*)Accz)[(size_t)row0 * 16 + i] = z;
        if (tid < nrow) Denz[row0 + tid] = 0.f;
    }

    // phase A: stage W_embed (64 rows) + x (pitch 68)
    stage_w64(We, Ws, tid);
    for (int i = tid; i < 64 * 16; i += 256) {
        int r = i >> 4, c4 = i & 15;
        int gr = row0 + r;
        float4 v = make_float4(0.f, 0.f, 0.f, 0.f);
        if (gr < M) v = ((const float4*)(x + (size_t)gr * 64))[c4];
        float* ap = As + r * 68 + c4 * 4;
        ap[0] = tf32f(v.x); ap[1] = tf32f(v.y); ap[2] = tf32f(v.z); ap[3] = tf32f(v.w);
    }
    __syncthreads();

    const int wid = tid >> 5, lane = tid & 31;
    const int wm = wid & 1, wn = wid >> 1;          // 2x4 warp grid, tile 32x32
    const int wrow = wm * 32, wcol = wn * 32;
    const int gid = lane >> 2, tig = lane & 3;

    float acc[2][4][4];
    ZACC(acc, 2, 4)
    mma_chunk64<2, 4>(As, 68, 0, Ws, wrow, wcol, gid, tig, acc);
    __syncthreads();   // phase-A reads complete before As/Ws overwrite

    // epilogue h: write gmem + restage tf32 into As (pitch AP)
#pragma unroll
    for (int nf = 0; nf < 4; ++nf) {
        const int c = wcol + nf * 8 + tig * 2;
        const float b0 = be[c], b1 = be[c + 1];
#pragma unroll
        for (int mf = 0; mf < 2; ++mf)
#pragma unroll
            for (int h = 0; h < 2; ++h) {
                const int rl = wrow + mf * 16 + h * 8 + gid;
                const float v0 = acc[mf][nf][2 * h] + b0;
                const float v1 = acc[mf][nf][2 * h + 1] + b1;
                const int gr = row0 + rl;
                if (gr < M)
                    *(float2*)(Hout + (size_t)gr * 128 + c) = make_float2(v0, v1);
                As[rl * AP + c]     = tf32f(v0);
                As[rl * AP + c + 1] = tf32f(v1);
            }
    }

#pragma unroll
    for (int ph = 0; ph < 2; ++ph) {
        const float* W    = ph ? Wr : Wl;
        const float* bias = ph ? br : bl;
        __half* C         = ph ? Cr : Cl;
        ZACC(acc, 2, 4)
#pragma unroll
        for (int kc = 0; kc < 2; ++kc) {
            __syncthreads();                       // guard prior Ws reads / As writes
            stage_w64(W + kc * 64 * 128, Ws, tid);
            __syncthreads();
            mma_chunk64<2, 4>(As, AP, kc * 64, Ws, wrow, wcol, gid, tig, acc);
        }
        write_c_h(C, bias, row0, wrow, wcol, gid, tig, acc, M);
    }
}

// ---------- dual transform with fused update + zero-after-read (BM=64, 3 CTAs/SM) ----------
__global__ __launch_bounds__(256, 3) void dual_upd(
    float* __restrict__ H, __half* __restrict__ Acc, float* __restrict__ Den,
    const float* __restrict__ ubias,
    const float* __restrict__ Wl, const float* __restrict__ bl,
    const float* __restrict__ Wr, const float* __restrict__ br,
    __half* __restrict__ Cl, __half* __restrict__ Cr, int M)
{
    extern __shared__ float sh[];
    float* As = sh;                  // 64 x AP
    float* Ws = sh + 64 * AP;        // 64 x WNP
    const int tid = threadIdx.x;
    const int row0 = blockIdx.x * 64;

    // stage A with fused update: h1 = h + relu(acc/den + ubias)
    for (int i = tid; i < 64 * 32; i += 256) {
        int r = i >> 5, c4 = i & 31;
        int gr = row0 + r;
        float4 hv = make_float4(0.f, 0.f, 0.f, 0.f);
        if (gr < M) {
            float inv = 1.f / (Den[gr] + 1e-16f);
            const __half2* ah = (const __half2*)Acc + (size_t)gr * 64 + c4 * 2;
            float2 a01 = __half22float2(ah[0]);
            float2 a23 = __half22float2(ah[1]);
            hv = ((const float4*)H)[(size_t)gr * 32 + c4];
            const float4 bb = ((const float4*)ubias)[c4];
            hv.x += fmaxf(a01.x * inv + bb.x, 0.f);
            hv.y += fmaxf(a01.y * inv + bb.y, 0.f);
            hv.z += fmaxf(a23.x * inv + bb.z, 0.f);
            hv.w += fmaxf(a23.y * inv + bb.w, 0.f);
            ((float4*)H)[(size_t)gr * 32 + c4] = hv;
        }
        float* ap = As + r * AP + c4 * 4;
        ap[0] = tf32f(hv.x); ap[1] = tf32f(hv.y); ap[2] = tf32f(hv.z); ap[3] = tf32f(hv.w);
    }
    __syncthreads();   // ALL acc/den reads for this block's rows are complete

    // zero-after-read: re-zero acc/den for the next edge pass
    {
        const uint4 z = make_uint4(0u, 0u, 0u, 0u);
        int nrow = min(64, M - row0);
        for (int i = tid; i < nrow * 16; i += 256)
            ((uint4*)Acc)[(size_t)row0 * 16 + i] = z;
        if (tid < nrow) Den[row0 + tid] = 0.f;
    }

    const int wid = tid >> 5, lane = tid & 31;
    const int wm = wid & 1, wn = wid >> 1;
    const int wrow = wm * 32, wcol = wn * 32;
    const int gid = lane >> 2, tig = lane & 3;

    float acc[2][4][4];
#pragma unroll
    for (int ph = 0; ph < 2; ++ph) {
        const float* W    = ph ? Wr : Wl;
        const float* bias = ph ? br : bl;
        __half* C         = ph ? Cr : Cl;
        ZACC(acc, 2, 4)
#pragma unroll
        for (int kc = 0; kc < 2; ++kc) {
            __syncthreads();
            stage_w64(W + kc * 64 * 128, Ws, tid);
            __syncthreads();
            mma_chunk64<2, 4>(As, AP, kc * 64, Ws, wrow, wcol, gid, tig, acc);
        }
        write_c_h(C, bias, row0, wrow, wcol, gid, tig, acc, M);
    }
}

// ---------- fused edge pass: warp per edge, fp16 xl/xr/acc ----------
__global__ void edge_kernel(const int* __restrict__ src, const int* __restrict__ dst,
                            const float* __restrict__ att)
{
    int e = (int)(((size_t)blockIdx.x * blockDim.x + threadIdx.x) >> 5);
    if (e >= NE) return;
    int ln = threadIdx.x & 31;
    int s = src[e], d = dst[e];
    // lane ln covers columns [4ln, 4ln+4)
    const __half2* xap = (const __half2*)g_xl + (size_t)s * 64 + ln * 2;
    const __half2* xbp = (const __half2*)g_xr + (size_t)d * 64 + ln * 2;
    __half2 xa2[2], xb2[2];
    *(uint2*)xa2 = *(const uint2*)xap;
    *(uint2*)xb2 = *(const uint2*)xbp;
    float2 xa01 = __half22float2(xa2[0]);
    float2 xa23 = __half22float2(xa2[1]);
    float2 xb01 = __half22float2(xb2[0]);
    float2 xb23 = __half22float2(xb2[1]);
    float4 at = ((const float4*)att)[ln];

    float vx = xa01.x + xb01.x; vx = vx > 0.f ? vx : 0.2f * vx;
    float vy = xa01.y + xb01.y; vy = vy > 0.f ? vy : 0.2f * vy;
    float vz = xa23.x + xb23.x; vz = vz > 0.f ? vz : 0.2f * vz;
    float vw = xa23.y + xb23.y; vw = vw > 0.f ? vw : 0.2f * vw;
    float p = vx * at.x + vy * at.y + vz * at.z + vw * at.w;
#pragma unroll
    for (int o = 16; o > 0; o >>= 1) p += __shfl_xor_sync(0xffffffffu, p, o);
    float e_ = __expf(p);
    if (ln == 0) atomicAdd(&g_den[d], e_);
    __half2* accd = (__half2*)g_acc + (size_t)d * 64 + ln * 2;
    atomicAdd(accd + 0, __floats2half2_rn(e_ * xa01.x, e_ * xa01.y));
    atomicAdd(accd + 1, __floats2half2_rn(e_ * xa23.x, e_ * xa23.y));
}

// ---------- mega head: BM=64, warp tile 32x32 grid 2x4, 2 CTAs/SM ----------
__global__ __launch_bounds__(256, 2) void head_kernel(
    const float* __restrict__ H, const __half* __restrict__ Acc, const float* __restrict__ Den,
    const float* __restrict__ ubias,
    const int* __restrict__ child, const int* __restrict__ parent,
    const float* __restrict__ ttab, const int* __restrict__ timei,
    const float* __restrict__ W_comb, const float* __restrict__ b_comb,
    const float* __restrict__ W_a1, const float* __restrict__ cadd,
    const float* __restrict__ W_a2, const float* __restrict__ b_a2,
    float* __restrict__ out, int M)
{
    extern __shared__ float sh[];
    float* As  = sh;                  // 64 x APH
    float* Ws  = sh + 64 * APH;       // 64 x WNP
    float* red = Ws + 64 * WNP;       // 4 x 64
    const int tid = threadIdx.x;
    const int row0 = blockIdx.x * 64;

    // stage cat(h2[child], h2[parent]|0), h2 = h1 + relu(acc/den + ubias)
    for (int i = tid; i < 64 * 64; i += 256) {
        int r = i >> 6, c4 = i & 63;
        int gr = row0 + r;
        float4 v = make_float4(0.f, 0.f, 0.f, 0.f);
        if (gr < M) {
            int cc = c4 < 32 ? c4 : c4 - 32;
            int ri = c4 < 32 ? child[gr] : parent[gr];
            if (ri >= 0) {
                float inv = 1.f / (Den[ri] + 1e-16f);
                const __half2* ah = (const __half2*)Acc + (size_t)ri * 64 + cc * 2;
                float2 a01 = __half22float2(ah[0]);
                float2 a23 = __half22float2(ah[1]);
                v = ((const float4*)H)[(size_t)ri * 32 + cc];
                float4 bb = ((const float4*)ubias)[cc];
                v.x += fmaxf(a01.x * inv + bb.x, 0.f);
                v.y += fmaxf(a01.y * inv + bb.y, 0.f);
                v.z += fmaxf(a23.x * inv + bb.z, 0.f);
                v.w += fmaxf(a23.y * inv + bb.w, 0.f);
            }
        }
        float* ap = As + r * APH + c4 * 4;
        ap[0] = tf32f(v.x); ap[1] = tf32f(v.y); ap[2] = tf32f(v.z); ap[3] = tf32f(v.w);
    }

    const int wid = tid >> 5, lane = tid & 31;
    const int wm = wid & 1, wn = wid >> 1;        // 2x4 warp grid, tile 32x32
    const int wrow = wm * 32, wcol = wn * 32;
    const int gid = lane >> 2, tig = lane & 3;

    float acc[2][4][4];
    ZACC(acc, 2, 4)

    // GEMM1: branch = cat @ W_comb  (K=256, 4 chunks)
#pragma unroll
    for (int kc = 0; kc < 4; ++kc) {
        __syncthreads();
        stage_w64(W_comb + kc * 64 * 128, Ws, tid);
        __syncthreads();
        mma_chunk64<2, 4>(As, APH, kc * 64, Ws, wrow, wcol, gid, tig, acc);
    }
    __syncthreads();   // GEMM1 As reads complete before overwrite

    // epilogue1: branch(+b_comb) -> As cols [0,128)
#pragma unroll
    for (int nf = 0; nf < 4; ++nf) {
        const int c = wcol + nf * 8 + tig * 2;
        const float b0 = b_comb[c], b1 = b_comb[c + 1];
#pragma unroll
        for (int mf = 0; mf < 2; ++mf)
#pragma unroll
            for (int h = 0; h < 2; ++h) {
                const int rl = wrow + mf * 16 + h * 8 + gid;
                As[rl * APH + c]     = tf32f(acc[mf][nf][2 * h]     + b0);
                As[rl * APH + c + 1] = tf32f(acc[mf][nf][2 * h + 1] + b1);
            }
    }
    // stage t_emb -> As cols [128,256)
    for (int i = tid; i < 64 * 32; i += 256) {
        int r = i >> 5, c4 = i & 31;
        int gr = row0 + r;
        float4 v = make_float4(0.f, 0.f, 0.f, 0.f);
        if (gr < M) {
            int t = timei[gr];
            v = ((const float4*)(ttab + (size_t)t * 128))[c4];
        }
        float* ap = As + r * APH + 128 + c4 * 4;
        ap[0] = tf32f(v.x); ap[1] = tf32f(v.y); ap[2] = tf32f(v.z); ap[3] = tf32f(v.w);
    }

    // GEMM2: hidden = relu(cat @ W_a1 + cadd)
    ZACC(acc, 2, 4)
#pragma unroll
    for (int kc = 0; kc < 4; ++kc) {
        __syncthreads();
        stage_w64(W_a1 + kc * 64 * 128, Ws, tid);
        __syncthreads();
        mma_chunk64<2, 4>(As, APH, kc * 64, Ws, wrow, wcol, gid, tig, acc);
    }

    // epilogue2: dot with W_a2
    float p[2][2] = {{0.f, 0.f}, {0.f, 0.f}};
#pragma unroll
    for (int nf = 0; nf < 4; ++nf) {
        const int c = wcol + nf * 8 + tig * 2;
        const float ca0 = cadd[c], ca1 = cadd[c + 1];
        const float w20 = W_a2[c], w21 = W_a2[c + 1];
#pragma unroll
        for (int mf = 0; mf < 2; ++mf)
#pragma unroll
            for (int h = 0; h < 2; ++h) {
                float v0 = fmaxf(acc[mf][nf][2 * h]     + ca0, 0.f);
                float v1 = fmaxf(acc[mf][nf][2 * h + 1] + ca1, 0.f);
                p[mf][h] += v0 * w20 + v1 * w21;
            }
    }
#pragma unroll
    for (int o = 1; o <= 2; o <<= 1)
#pragma unroll
        for (int mf = 0; mf < 2; ++mf)
#pragma unroll
            for (int h = 0; h < 2; ++h)
                p[mf][h] += __shfl_xor_sync(0xffffffffu, p[mf][h], o);

    __syncthreads();
    if (tig == 0) {
#pragma unroll
        for (int mf = 0; mf < 2; ++mf)
#pragma unroll
            for (int h = 0; h < 2; ++h)
                red[wn * 64 + wrow + mf * 16 + h * 8 + gid] = p[mf][h];
    }
    __syncthreads();
    if (tid < 64) {
        int gr = row0 + tid;
        if (gr < M)
            out[gr] = red[tid] + red[64 + tid] + red[128 + tid] + red[192 + tid] + b_a2[0];
    }
}

// ---------------- fused context precompute ----------------
__global__ void ctx_cadd_kernel(const float* __restrict__ focal, const float* __restrict__ W_seq,
                                const float* __restrict__ b_seq,
                                const float* __restrict__ W_a1, const float* __restrict__ b_a1)
{
    __shared__ float cs[128];
    int j = threadIdx.x;
    float s = b_seq[j];
    for (int d = 0; d < DD; ++d) s += focal[d] * W_seq[d * 128 + j];
    cs[j] = s;
    __syncthreads();
    float t = b_a1[j];
    for (int k = 0; k < 128; ++k) t += cs[k] * W_a1[(256 + k) * 128 + j];
    g_cadd[j] = t;
}

// ---------------- launch ----------------
extern "C" void kernel_launch(void* const* d_in, const int* in_sizes, int n_in,
                              void* d_out, int out_size)
{
    const float* x       = (const float*)d_in[0];
    const int*   ei      = (const int*)  d_in[1];
    const float* focal   = (const float*)d_in[2];
    const int*   child   = (const int*)  d_in[3];
    const int*   parent  = (const int*)  d_in[4];
    const int*   timei   = (const int*)  d_in[5];
    const float* W_embed = (const float*)d_in[6];
    const float* b_embed = (const float*)d_in[7];
    const float* bu_Wl   = (const float*)d_in[8];
    const float* bu_bl   = (const float*)d_in[9];
    const float* bu_Wr   = (const float*)d_in[10];
    const float* bu_br   = (const float*)d_in[11];
    const float* bu_att  = (const float*)d_in[12];
    const float* bu_bias = (const float*)d_in[13];
    const float* td_Wl   = (const float*)d_in[14];
    const float* td_bl   = (const float*)d_in[15];
    const float* td_Wr   = (const float*)d_in[16];
    const float* td_br   = (const float*)d_in[17];
    const float* td_att  = (const float*)d_in[18];
    const float* td_bias = (const float*)d_in[19];
    const float* ttab    = (const float*)d_in[20];
    const float* W_comb  = (const float*)d_in[21];
    const float* b_comb  = (const float*)d_in[22];
    const float* W_a1    = (const float*)d_in[23];
    const float* b_a1    = (const float*)d_in[24];
    const float* W_a2    = (const float*)d_in[25];
    const float* b_a2    = (const float*)d_in[26];
    const float* W_seq   = (const float*)d_in[27];
    const float* b_seq   = (const float*)d_in[28];
    float* out = (float*)d_out;

    const int SM_DUAL = (64 * AP + 64 * WNP) * 4;             // 68,608 B  (3 CTAs/SM)
    const int SM_HEAD = (64 * APH + 64 * WNP + 256) * 4;      // 102,400 B (2 CTAs/SM)
    cudaFuncSetAttribute(embed_dual,  cudaFuncAttributeMaxDynamicSharedMemorySize, SM_DUAL);
    cudaFuncSetAttribute(dual_upd,    cudaFuncAttributeMaxDynamicSharedMemorySize, SM_DUAL);
    cudaFuncSetAttribute(head_kernel, cudaFuncAttributeMaxDynamicSharedMemorySize, SM_HEAD);

    float *hp, *denp, *caddp;
    __half *xlp, *xrp, *accp;
    cudaGetSymbolAddress((void**)&hp,    g_h);
    cudaGetSymbolAddress((void**)&xlp,   g_xl);
    cudaGetSymbolAddress((void**)&xrp,   g_xr);
    cudaGetSymbolAddress((void**)&accp,  g_acc);
    cudaGetSymbolAddress((void**)&denp,  g_den);
    cudaGetSymbolAddress((void**)&caddp, g_cadd);

    const int GEMM_BLKS_N = (NN + 63) / 64;
    const int HEAD_BLKS   = (NA + 63) / 64;
    const int EDGE_BLKS   = (NE + 7) / 8;

    // 0) context fold (tiny, no deps on pipeline)
    ctx_cadd_kernel<<<1, 128>>>(focal, W_seq, b_seq, W_a1, b_a1);

    // 1) embed + bottom-up transforms + acc/den zeroing (src = row1, dst = row0)
    embed_dual<<<GEMM_BLKS_N, 256, SM_DUAL>>>(x, W_embed, b_embed,
                                              bu_Wl, bu_bl, bu_Wr, bu_br,
                                              hp, xlp, xrp, accp, denp, NN);
    edge_kernel<<<EDGE_BLKS, 256>>>(ei + NE, ei, bu_att);

    // 2) update1 fused + top-down transforms + zero-after-read (src = row0, dst = row1)
    dual_upd<<<GEMM_BLKS_N, 256, SM_DUAL>>>(hp, accp, denp, bu_bias,
                                            td_Wl, td_bl, td_Wr, td_br,
                                            xlp, xrp, NN);
    edge_kernel<<<EDGE_BLKS, 256>>>(ei, ei + NE, td_att);

    // 3) head with on-the-fly update2
    head_kernel<<<HEAD_BLKS, 256, SM_HEAD>>>(hp, accp, denp, td_bias,
                                             child, parent, ttab, timei,
                                             W_comb, b_comb, W_a1, caddp,
                                             W_a2, b_a2, out, NA);
}